// round 7
// baseline (speedup 1.0000x reference)
#include <cuda_runtime.h>
#include <cstdint>
#include <cstddef>

#define INDIM 1024
#define OUTDIM 1024

// Packed Wrr: g_wrr2[er*128 + lane*4 + oi] = wrr[er*128 + oi*32 + lane]
__device__ float g_wrr2[32 * 128];

__global__ void phm_prep(const float* __restrict__ wrr) {
    int idx = blockIdx.x * blockDim.x + threadIdx.x;
    if (idx < 4096) {
        int er = idx >> 7, t = idx & 127;
        int l = t >> 2, oi = t & 3;
        g_wrr2[idx] = wrr[er * 128 + oi * 32 + l];
    }
}

__device__ __forceinline__ unsigned long long pack2(float lo, float hi) {
    unsigned long long r;
    asm("mov.b64 %0, {%1, %2};" : "=l"(r) : "f"(lo), "f"(hi));
    return r;
}
__device__ __forceinline__ void unpack2(unsigned long long v, float &lo, float &hi) {
    asm("mov.b64 {%0, %1}, %2;" : "=f"(lo), "=f"(hi) : "l"(v));
}
__device__ __forceinline__ void fma2(unsigned long long &d, unsigned long long a, unsigned long long b) {
    asm("fma.rn.f32x2 %0, %1, %2, %0;" : "+l"(d) : "l"(a), "l"(b));
}

__global__ void __launch_bounds__(128, 6)
phm_main(const float* __restrict__ x,
         const float* __restrict__ wrl,   // [8][128][4]
         const float* __restrict__ wlf,   // [8][8][8]
         float* __restrict__ out,
         int nrows)
{
    // Wrl: [rp][e][i4][rlo][4]; rp-stride 2096 (mod32=16), e-stride 260 (mod32=4)
    // -> per 8-lane group start banks {0,16,4,20,8,24,12,28}: conflict-free.
    __shared__ __align__(16) float s_wrl2[2 * 2096];
    __shared__ __align__(16) float s_wl[8 * 68];                 // [e][a*8+c], pad 68
    __shared__ __align__(16) unsigned long long s_u[4][2][4][34];// [warp][q][cp][er pad34]
    __shared__ __align__(16) float s_x[4][2][2][2][36];          // [warp][buf][sl][q][a*4 pad36]

    const int tid  = threadIdx.x;
    const int lane = tid & 31;
    const int wid  = tid >> 5;
    const int q  = lane >> 4;   // row within warp pair
    const int p  = lane & 15;
    const int e  = p >> 1;      // ensemble index
    const int rp = p & 1;       // r-pair: r in {2rp, 2rp+1}

    // ---- stage weights (once per block) ----
    #pragma unroll
    for (int k = 0; k < 32; k++) {
        int idx = tid + 128 * k;                  // 4096
        int ee = idx >> 9;
        int rem = idx & 511;
        int i = rem >> 2, r = rem & 3;
        s_wrl2[(r >> 1) * 2096 + ee * 260 + (i >> 2) * 8 + (r & 1) * 4 + (i & 3)] = wrl[idx];
    }
    #pragma unroll
    for (int k = 0; k < 4; k++) {
        int idx = tid + 128 * k;                  // 512
        s_wl[(idx >> 6) * 68 + (idx & 63)] = wlf[idx];
    }
    __syncthreads();

    int row0 = blockIdx.x * 8 + wid * 2;
    if (row0 >= nrows) return;

    // loader role: lane (q,p): row q, a = p&7, slice-parity sl = p>>3
    const float* xld = x + (size_t)min(row0 + q, nrows - 1) * INDIM
                         + (p & 7) * 128 + (p >> 3) * 4;
    float* sxw = &s_x[wid][0][0][0][0];
    const int sx_off = (p >> 3) * 72 + q * 36 + (p & 7) * 4;

    // ---- Phase A: acc[a][rlo], packed over i-parity ----
    unsigned long long acc[16];
    #pragma unroll
    for (int k = 0; k < 16; k++) acc[k] = 0ull;

    {   // prologue: i4-pair 0 -> buf0
        float4 t0 = *(const float4*)(xld);
        *(float4*)(sxw + sx_off) = t0;
    }
    float4 xq = *(const float4*)(xld + 8);   // pair 1 chunk

    const float* wvb = s_wrl2 + rp * 2096 + e * 260;
    const float* sxr = &s_x[wid][0][0][0][0] + q * 36;

    #pragma unroll 1
    for (int t = 0; t < 16; t++) {
        __syncwarp();
        if (t < 15) {
            *(float4*)(sxw + ((t + 1) & 1) * 144 + sx_off) = xq;
            int nxt = (t + 2 <= 15) ? (t + 2) : 15;
            xq = *(const float4*)(xld + nxt * 8);
        }
        #pragma unroll
        for (int sl = 0; sl < 2; sl++) {
            const int i4 = t * 2 + sl;
            ulonglong2 wv_r0 = *(const ulonglong2*)(wvb + i4 * 8);      // r = 2rp
            ulonglong2 wv_r1 = *(const ulonglong2*)(wvb + i4 * 8 + 4);  // r = 2rp+1
            const float* xb = sxr + (t & 1) * 144 + sl * 72;
            #pragma unroll
            for (int a = 0; a < 8; a++) {
                ulonglong2 xv = *(const ulonglong2*)(xb + a * 4);   // q-broadcast
                fma2(acc[a*2+0], xv.x, wv_r0.x); fma2(acc[a*2+0], xv.y, wv_r0.y);
                fma2(acc[a*2+1], xv.x, wv_r1.x); fma2(acc[a*2+1], xv.y, wv_r1.y);
            }
        }
    }

    // ---- Phase B: uc[rlo][cp] = sum_a y1[a][rlo] * Wl[e][a][c] (in-lane) ----
    unsigned long long uc[8];
    #pragma unroll
    for (int k = 0; k < 8; k++) uc[k] = 0ull;
    const float* wlb = s_wl + e * 68;
    #pragma unroll
    for (int a = 0; a < 8; a++) {
        ulonglong2 W01 = *(const ulonglong2*)(wlb + a * 8);
        ulonglong2 W23 = *(const ulonglong2*)(wlb + a * 8 + 4);
        #pragma unroll
        for (int rl = 0; rl < 2; rl++) {
            float lo, hi; unpack2(acc[a*2+rl], lo, hi);
            float y = lo + hi;
            unsigned long long yd = pack2(y, y);
            fma2(uc[rl*4+0], yd, W01.x);
            fma2(uc[rl*4+1], yd, W01.y);
            fma2(uc[rl*4+2], yd, W23.x);
            fma2(uc[rl*4+3], yd, W23.y);
        }
    }
    {
        const int er0 = e * 4 + rp * 2;
        #pragma unroll
        for (int rl = 0; rl < 2; rl++)
            #pragma unroll
            for (int cp = 0; cp < 4; cp++)
                s_u[wid][q][cp][er0 + rl] = uc[rl * 4 + cp];
    }
    __syncwarp();

    // ---- Phase C: per-row passes; out[o,c] = sum_er u[er,c]*Wrr[er,o] ----
    const float* wrb = g_wrr2 + lane * 4;
    #pragma unroll 1
    for (int pass = 0; pass < 2; pass++) {
        unsigned long long A[16];     // [oi][cp]
        #pragma unroll
        for (int k = 0; k < 16; k++) A[k] = 0ull;
        const unsigned long long* ub = &s_u[wid][pass][0][0];

        #pragma unroll 2
        for (int er2 = 0; er2 < 16; er2++) {
            float4 wa = *(const float4*)(wrb + (er2 * 2 + 0) * 128);   // er even, L1-hit
            float4 wc = *(const float4*)(wrb + (er2 * 2 + 1) * 128);   // er odd
            ulonglong2 U0 = *(const ulonglong2*)(ub + 0 * 34 + er2 * 2);  // broadcast
            ulonglong2 U1 = *(const ulonglong2*)(ub + 1 * 34 + er2 * 2);
            ulonglong2 U2 = *(const ulonglong2*)(ub + 2 * 34 + er2 * 2);
            ulonglong2 U3 = *(const ulonglong2*)(ub + 3 * 34 + er2 * 2);
            unsigned long long wd;
            wd = pack2(wa.x, wa.x); fma2(A[ 0],wd,U0.x); fma2(A[ 1],wd,U1.x); fma2(A[ 2],wd,U2.x); fma2(A[ 3],wd,U3.x);
            wd = pack2(wa.y, wa.y); fma2(A[ 4],wd,U0.x); fma2(A[ 5],wd,U1.x); fma2(A[ 6],wd,U2.x); fma2(A[ 7],wd,U3.x);
            wd = pack2(wa.z, wa.z); fma2(A[ 8],wd,U0.x); fma2(A[ 9],wd,U1.x); fma2(A[10],wd,U2.x); fma2(A[11],wd,U3.x);
            wd = pack2(wa.w, wa.w); fma2(A[12],wd,U0.x); fma2(A[13],wd,U1.x); fma2(A[14],wd,U2.x); fma2(A[15],wd,U3.x);
            wd = pack2(wc.x, wc.x); fma2(A[ 0],wd,U0.y); fma2(A[ 1],wd,U1.y); fma2(A[ 2],wd,U2.y); fma2(A[ 3],wd,U3.y);
            wd = pack2(wc.y, wc.y); fma2(A[ 4],wd,U0.y); fma2(A[ 5],wd,U1.y); fma2(A[ 6],wd,U2.y); fma2(A[ 7],wd,U3.y);
            wd = pack2(wc.z, wc.z); fma2(A[ 8],wd,U0.y); fma2(A[ 9],wd,U1.y); fma2(A[10],wd,U2.y); fma2(A[11],wd,U3.y);
            wd = pack2(wc.w, wc.w); fma2(A[12],wd,U0.y); fma2(A[13],wd,U1.y); fma2(A[14],wd,U2.y); fma2(A[15],wd,U3.y);
        }

        if (row0 + pass < nrows) {
            float* og = out + (size_t)(row0 + pass) * OUTDIM;
            #pragma unroll
            for (int oi = 0; oi < 4; oi++) {
                int o = lane + oi * 32;
                ulonglong2 v0; v0.x = A[oi*4+0]; v0.y = A[oi*4+1];
                ulonglong2 v1; v1.x = A[oi*4+2]; v1.y = A[oi*4+3];
                *(ulonglong2*)(og + o * 8)     = v0;
                *(ulonglong2*)(og + o * 8 + 4) = v1;
            }
        }
    }
}

extern "C" void kernel_launch(void* const* d_in, const int* in_sizes, int n_in,
                              void* d_out, int out_size) {
    const float* x   = (const float*)d_in[0];
    const float* wrl = (const float*)d_in[1];
    const float* wrr = (const float*)d_in[2];
    const float* wlf = (const float*)d_in[3];
    float* out = (float*)d_out;

    int nrows = in_sizes[0] / INDIM;               // B*S = 8192
    phm_prep<<<16, 256>>>(wrr);
    int grid = (nrows + 7) / 8;                    // 8 rows per block (4 warps x 2 rows)
    phm_main<<<grid, 128>>>(x, wrl, wlf, out, nrows);
}

// round 11
// speedup vs baseline: 2.0105x; 2.0105x over previous
#include <cuda_runtime.h>
#include <cstdint>
#include <cstddef>

// PHMLinear via mma.sync tf32 (sm_80+ path; tcgen05 unavailable under compute_100).
// Per CTA tile = 16 rows:
//  MMA1: y1[(row,a), er] = sum_i x[row,a*128+i]*Wrl[e,i,r]   M=128,N=32,K=128
//  PhB : u[(row,c), er]  = sum_a y1[(row,a),er]*Wl[e,a,c]    CUDA cores, u stays in regs
//  MMA2: out[(row,c), o] = sum_er u[(row,c),er]*Wrr[e,r,o]   M=128,N=128,K=32

__device__ float g_wrrT[128 * 32];   // [o][er], tf32-rounded

__device__ __forceinline__ uint32_t to_tf32(float f) {
    uint32_t r;
    asm("cvt.rna.tf32.f32 %0, %1;" : "=r"(r) : "f"(f));
    return r;
}

__global__ void phm_prep(const float* __restrict__ wrr) {
    int idx = blockIdx.x * blockDim.x + threadIdx.x;
    if (idx < 4096) {
        int o = idx >> 5, er = idx & 31;
        g_wrrT[idx] = __uint_as_float(to_tf32(wrr[er * 128 + o]));
    }
}

__device__ __forceinline__ void mma8(float& d0, float& d1, float& d2, float& d3,
                                     uint32_t a0, uint32_t a1, uint32_t a2, uint32_t a3,
                                     uint32_t b0, uint32_t b1) {
    asm volatile(
        "mma.sync.aligned.m16n8k8.row.col.f32.tf32.tf32.f32 "
        "{%0,%1,%2,%3}, {%4,%5,%6,%7}, {%8,%9}, {%0,%1,%2,%3};"
        : "+f"(d0), "+f"(d1), "+f"(d2), "+f"(d3)
        : "r"(a0), "r"(a1), "r"(a2), "r"(a3), "r"(b0), "r"(b1));
}

__global__ void __launch_bounds__(128)
phm_tc(const float* __restrict__ x,
       const float* __restrict__ wrl,   // [8][128][4]
       const float* __restrict__ wlf,   // [8][8][8]
       float* __restrict__ out,
       int nrows)
{
    // Region A: x chunk [128 vrow][32 pad36] -> y1T [32 er][128 vrow pad132] -> D_s [128 t][32 pad36]
    __shared__ __align__(16) float sA[4608];
    // Region B: WrlT [32 er][128 i pad132] -> WrrT [128 o][32 er pad36]
    __shared__ __align__(16) float sB[4608];
    __shared__ __align__(16) float s_wl[512];   // [e][c][a]

    const int tid  = threadIdx.x;
    const int lane = tid & 31;
    const int wid  = tid >> 5;
    const int g  = lane >> 2;   // mma groupID
    const int tg = lane & 3;    // mma threadID-in-group
    int row0 = blockIdx.x * 16;
    if (row0 >= nrows) return;

    // ---- stage WrlT (tf32) + wl ----
    #pragma unroll
    for (int k = 0; k < 32; k++) {
        int m = tid + 128 * k;                 // [e][i][r] row-major
        int e = m >> 9, i = (m & 511) >> 2, r = m & 3;
        sB[(e * 4 + r) * 132 + i] = __uint_as_float(to_tf32(wrl[m]));
    }
    #pragma unroll
    for (int k = 0; k < 4; k++) {
        int m = tid + 128 * k;                 // [e][a][c]
        int e = m >> 6, a = (m >> 3) & 7, c = m & 7;
        s_wl[e * 64 + c * 8 + a] = wlf[m];
    }
    __syncthreads();

    const int mbase = wid * 32;

    // ---- MMA1: y accum [mt][nt][4] ----
    float y[2][4][4];
    #pragma unroll
    for (int mt = 0; mt < 2; mt++)
        #pragma unroll
        for (int nt = 0; nt < 4; nt++)
            #pragma unroll
            for (int j = 0; j < 4; j++) y[mt][nt][j] = 0.0f;

    #pragma unroll 1
    for (int kc = 0; kc < 4; kc++) {
        // stage x chunk [vrow][i' 32] pad 36, tf32
        #pragma unroll
        for (int k = 0; k < 8; k++) {
            int f4 = tid + 128 * k;            // 1024 float4
            int vrow = f4 >> 3, i4 = f4 & 7;
            int row = row0 + (vrow >> 3);
            if (row >= nrows) row = nrows - 1;
            float4 v = *(const float4*)(x + (size_t)row * 1024 + (vrow & 7) * 128 + kc * 32 + i4 * 4);
            v.x = __uint_as_float(to_tf32(v.x));
            v.y = __uint_as_float(to_tf32(v.y));
            v.z = __uint_as_float(to_tf32(v.z));
            v.w = __uint_as_float(to_tf32(v.w));
            *(float4*)(sA + vrow * 36 + i4 * 4) = v;
        }
        __syncthreads();
        #pragma unroll
        for (int kt = 0; kt < 4; kt++) {
            uint32_t b[4][2];
            #pragma unroll
            for (int nt = 0; nt < 4; nt++) {
                const float* bb = sB + (nt * 8 + g) * 132 + kc * 32 + kt * 8 + tg;
                b[nt][0] = __float_as_uint(bb[0]);
                b[nt][1] = __float_as_uint(bb[4]);
            }
            #pragma unroll
            for (int mt = 0; mt < 2; mt++) {
                const float* xa = sA + (mt * 16) * 36 + mbase * 36 + kt * 8 + tg;
                uint32_t a0 = __float_as_uint(xa[g * 36]);
                uint32_t a1 = __float_as_uint(xa[(g + 8) * 36]);
                uint32_t a2 = __float_as_uint(xa[g * 36 + 4]);
                uint32_t a3 = __float_as_uint(xa[(g + 8) * 36 + 4]);
                #pragma unroll
                for (int nt = 0; nt < 4; nt++)
                    mma8(y[mt][nt][0], y[mt][nt][1], y[mt][nt][2], y[mt][nt][3],
                         a0, a1, a2, a3, b[nt][0], b[nt][1]);
            }
        }
        __syncthreads();
    }

    // ---- write y1T [er][vrow pad132] into region A (x dead) ----
    #pragma unroll
    for (int mt = 0; mt < 2; mt++)
        #pragma unroll
        for (int nt = 0; nt < 4; nt++) {
            int vr = mbase + mt * 16 + g;
            int er = nt * 8 + tg * 2;
            sA[er * 132 + vr]           = y[mt][nt][0];
            sA[(er + 1) * 132 + vr]     = y[mt][nt][1];
            sA[er * 132 + vr + 8]       = y[mt][nt][2];
            sA[(er + 1) * 132 + vr + 8] = y[mt][nt][3];
        }

    // ---- stage WrrT [o][er pad36] into region B (WrlT dead) ----
    #pragma unroll
    for (int k = 0; k < 8; k++) {
        int f4 = tid + 128 * k;                // 1024 float4
        int o = f4 >> 3, e4 = f4 & 7;
        *(float4*)(sB + o * 36 + e4 * 4) = *(const float4*)(g_wrrT + o * 32 + e4 * 4);
    }
    __syncthreads();

    // ---- Phase B: u[rp][e] for this lane's (g=c, tg); er = 4e+tg; t = wid*32+rp*8+g ----
    uint32_t uu[4][8];
    #pragma unroll
    for (int e = 0; e < 8; e++) {
        int er = 4 * e + tg;
        float4 w0 = *(const float4*)(s_wl + e * 64 + g * 8);
        float4 w1 = *(const float4*)(s_wl + e * 64 + g * 8 + 4);
        #pragma unroll
        for (int rp = 0; rp < 4; rp++) {
            int vb = (wid * 4 + rp) * 8;
            float4 y0 = *(const float4*)(sA + er * 132 + vb);
            float4 y1v = *(const float4*)(sA + er * 132 + vb + 4);
            float u = y0.x * w0.x + y0.y * w0.y + y0.z * w0.z + y0.w * w0.w
                    + y1v.x * w1.x + y1v.y * w1.y + y1v.z * w1.z + y1v.w * w1.w;
            uu[rp][e] = to_tf32(u);
        }
    }
    __syncthreads();   // y1T reads done before D_s overlays region A

    // ---- MMA2 in 4 N-quarters + epilogue ----
    #pragma unroll 1
    for (int qn = 0; qn < 4; qn++) {
        float d[2][4][4];
        #pragma unroll
        for (int mt = 0; mt < 2; mt++)
            #pragma unroll
            for (int nl = 0; nl < 4; nl++)
                #pragma unroll
                for (int j = 0; j < 4; j++) d[mt][nl][j] = 0.0f;

        #pragma unroll
        for (int kt = 0; kt < 4; kt++)
            #pragma unroll
            for (int nl = 0; nl < 4; nl++) {
                int o = qn * 32 + nl * 8 + g;
                const float* bb = sB + o * 36 + kt * 8 + tg;
                uint32_t b0 = __float_as_uint(bb[0]);
                uint32_t b1 = __float_as_uint(bb[4]);
                #pragma unroll
                for (int mt = 0; mt < 2; mt++)
                    mma8(d[mt][nl][0], d[mt][nl][1], d[mt][nl][2], d[mt][nl][3],
                         uu[2 * mt][2 * kt], uu[2 * mt + 1][2 * kt],
                         uu[2 * mt][2 * kt + 1], uu[2 * mt + 1][2 * kt + 1],
                         b0, b1);
            }

        // D -> D_s[t][o' pad36] (region A)
        #pragma unroll
        for (int mt = 0; mt < 2; mt++)
            #pragma unroll
            for (int nl = 0; nl < 4; nl++) {
                int t = mbase + mt * 16 + g;
                int oc = nl * 8 + tg * 2;
                sA[t * 36 + oc]           = d[mt][nl][0];
                sA[t * 36 + oc + 1]       = d[mt][nl][1];
                sA[(t + 8) * 36 + oc]     = d[mt][nl][2];
                sA[(t + 8) * 36 + oc + 1] = d[mt][nl][3];
            }
        __syncthreads();

        // remap: out[row0+r][(qn*32+op)*8 + j4*4 + 0..3]
        #pragma unroll
        for (int ii = 0; ii < 8; ii++) {
            int f4 = ii * 128 + tid;           // 1024 float4 per quarter
            int r = f4 >> 6;
            int rem = f4 & 63;
            int op = rem >> 1, j4 = rem & 1;
            if (row0 + r < nrows) {
                float4 v;
                v.x = sA[(r * 8 + j4 * 4 + 0) * 36 + op];
                v.y = sA[(r * 8 + j4 * 4 + 1) * 36 + op];
                v.z = sA[(r * 8 + j4 * 4 + 2) * 36 + op];
                v.w = sA[(r * 8 + j4 * 4 + 3) * 36 + op];
                *(float4*)(out + (size_t)(row0 + r) * 1024 + qn * 256 + op * 8 + j4 * 4) = v;
            }
        }
        __syncthreads();
    }
}

extern "C" void kernel_launch(void* const* d_in, const int* in_sizes, int n_in,
                              void* d_out, int out_size) {
    const float* x   = (const float*)d_in[0];
    const float* wrl = (const float*)d_in[1];
    const float* wrr = (const float*)d_in[2];
    const float* wlf = (const float*)d_in[3];
    float* out = (float*)d_out;

    int nrows = in_sizes[0] / 1024;          // B*S = 8192
    phm_prep<<<16, 256>>>(wrr);
    int grid = (nrows + 15) / 16;            // 16 rows per CTA
    phm_tc<<<grid, 128>>>(x, wrl, wlf, out, nrows);
}